// round 1
// baseline (speedup 1.0000x reference)
#include <cuda_runtime.h>

#define NN 100000
#define EE 1600000
#define CC 8
#define HH 64
#define BB 16
#define NFEAT 140
#define CFEAT 18
#define OPED 64
#define INDIM 222
#define ALPHAC 0.2f
#define ROWS (CC*NN)
#define GRP 8

// ---------------- device scratch (no runtime allocation allowed) ----------------
__device__ float g_x [(size_t)ROWS*HH];   // current node states  [c][n][h]
__device__ float g_xd[(size_t)ROWS*HH];   // x @ Wd (SpMM input)
__device__ float g_y [(size_t)ROWS*HH];   // SpMM output
__device__ float g_xp[(size_t)ROWS*HH];   // layer-0 x @ Wp + bp
__device__ int   g_rowptr[NN+1];
__device__ int   g_wptr[NN];
__device__ int   g_col[2*EE];
__device__ float g_pooled[BB*CC*HH];

__device__ __forceinline__ float lrelu(float v){ return v > 0.f ? v : ALPHAC*v; }

__device__ __forceinline__ float warp_sum(float v){
  v += __shfl_xor_sync(0xffffffffu, v, 16);
  v += __shfl_xor_sync(0xffffffffu, v, 8);
  v += __shfl_xor_sync(0xffffffffu, v, 4);
  v += __shfl_xor_sync(0xffffffffu, v, 2);
  v += __shfl_xor_sync(0xffffffffu, v, 1);
  return v;
}

// ---------------- CSR build (A + A^T), rebuilt every call ----------------
__global__ void k_zero_counts() {
  int i = blockIdx.x*blockDim.x + threadIdx.x;
  if (i < NN) g_wptr[i] = 0;
}

__global__ void k_count(const int* __restrict__ src, const int* __restrict__ dst) {
  int e = blockIdx.x*blockDim.x + threadIdx.x;
  if (e < EE) {
    atomicAdd(&g_wptr[dst[e]], 1);
    atomicAdd(&g_wptr[src[e]], 1);
  }
}

__global__ void k_scan() {
  __shared__ int ss[1024];
  int t = threadIdx.x;
  const int CH = (NN + 1023) / 1024;          // 98
  int lo = t*CH;
  int hi = lo + CH; if (hi > NN) hi = NN;
  int s = 0;
  for (int i = lo; i < hi && i < NN; i++) s += g_wptr[i];
  ss[t] = s;
  __syncthreads();
  for (int off = 1; off < 1024; off <<= 1) {
    int v = (t >= off) ? ss[t-off] : 0;
    __syncthreads();
    ss[t] += v;
    __syncthreads();
  }
  int run = (t == 0) ? 0 : ss[t-1];
  for (int i = lo; i < hi && i < NN; i++) {
    int cv = g_wptr[i];
    g_rowptr[i] = run;
    g_wptr[i]   = run;   // write cursor for fill
    run += cv;
  }
  if (t == 1023) g_rowptr[NN] = ss[1023];
}

__global__ void k_fill(const int* __restrict__ src, const int* __restrict__ dst) {
  int e = blockIdx.x*blockDim.x + threadIdx.x;
  if (e < EE) {
    int s = src[e], d = dst[e];
    int p = atomicAdd(&g_wptr[d], 1);  g_col[p] = s;
    int q = atomicAdd(&g_wptr[s], 1);  g_col[q] = d;
  }
}

// ---------------- layer 0 fused feature-join + projections ----------------
// xd0 = x0 @ Wd0, xp0 = x0 @ Wp0 + bp0   with x0 = [op_emb | node_feats | cfg_feats]
#define L0_NT 4
__global__ void k_layer0(const float* __restrict__ node_feats,
                         const float* __restrict__ config_feats,
                         const int*   __restrict__ op_ids,
                         const float* __restrict__ op_emb,
                         const float* __restrict__ Wd,
                         const float* __restrict__ Wp,
                         const float* __restrict__ bp) {
  __shared__ float sBase[L0_NT*204];
  __shared__ float sCf[L0_NT*CC*CFEAT];
  int tid = threadIdx.x;
  int nl = tid >> 6;          // node within tile (0..3)
  int h  = tid & 63;          // output feature
  const int ntiles = NN / L0_NT;
  for (int tile = blockIdx.x; tile < ntiles; tile += gridDim.x) {
    int n0 = tile * L0_NT;
    for (int i = tid; i < L0_NT*204; i += blockDim.x) {
      int ln = i / 204; int d = i - ln*204;
      int n = n0 + ln;
      sBase[i] = (d < OPED) ? op_emb[op_ids[n]*OPED + d]
                            : node_feats[(size_t)n*NFEAT + (d - OPED)];
    }
    for (int i = tid; i < L0_NT*CC*CFEAT; i += blockDim.x) {
      int ln = i / (CC*CFEAT); int rem = i - ln*(CC*CFEAT);
      sCf[i] = config_feats[(size_t)(n0+ln)*CC*CFEAT + rem];
    }
    __syncthreads();
    {
      int n = n0 + nl;
      float accD = 0.f, accP = 0.f;
      const float* bptr = sBase + nl*204;
      #pragma unroll 4
      for (int d = 0; d < 204; d++) {
        float b = bptr[d];
        accD += b * __ldg(Wd + d*HH + h);
        accP += b * __ldg(Wp + d*HH + h);
      }
      float bpv = __ldg(bp + h);
      #pragma unroll
      for (int c = 0; c < CC; c++) {
        float aD = accD, aP = accP + bpv;
        const float* cf = sCf + (nl*CC + c)*CFEAT;
        #pragma unroll
        for (int j = 0; j < CFEAT; j++) {
          float f = cf[j];
          aD += f * __ldg(Wd + (204+j)*HH + h);
          aP += f * __ldg(Wp + (204+j)*HH + h);
        }
        size_t row = (size_t)c*NN + n;
        g_xd[row*HH + h] = aD;
        g_xp[row*HH + h] = aP;
      }
    }
    __syncthreads();
  }
}

// ---------------- SpMM: g_y = (A+A^T) * g_xd, one warp per (node,config) ----------------
__global__ void k_spmm() {
  int gw   = (blockIdx.x*blockDim.x + threadIdx.x) >> 5;
  int lane = threadIdx.x & 31;
  int nw   = (gridDim.x*blockDim.x) >> 5;
  for (int p = gw; p < ROWS; p += nw) {
    int c = p / NN;
    int n = p - c*NN;
    int beg = g_rowptr[n], end = g_rowptr[n+1];
    const float2* xs = (const float2*)(g_xd + (size_t)c*NN*HH);
    float a0 = 0.f, a1 = 0.f;
    int e = beg;
    for (; e + 4 <= end; e += 4) {
      int s0 = __ldg(g_col + e);
      int s1 = __ldg(g_col + e + 1);
      int s2 = __ldg(g_col + e + 2);
      int s3 = __ldg(g_col + e + 3);
      float2 v0 = xs[(size_t)s0*32 + lane];
      float2 v1 = xs[(size_t)s1*32 + lane];
      float2 v2 = xs[(size_t)s2*32 + lane];
      float2 v3 = xs[(size_t)s3*32 + lane];
      a0 += (v0.x + v1.x) + (v2.x + v3.x);
      a1 += (v0.y + v1.y) + (v2.y + v3.y);
    }
    for (; e < end; e++) {
      int s = __ldg(g_col + e);
      float2 v = xs[(size_t)s*32 + lane];
      a0 += v.x; a1 += v.y;
    }
    float2* o = (float2*)(g_y + (size_t)p*HH);
    o[lane] = make_float2(a0, a1);
  }
}

// ---------------- register-tiled 64x64 matvec over 8 rows ----------------
__device__ __forceinline__ void matvec_grp(const float* __restrict__ W, const float* rb,
                                           int lane, float a0[GRP], float a1[GRP]) {
  #pragma unroll 4
  for (int d4 = 0; d4 < HH; d4 += 4) {
    float w00 = __ldg(W + (d4+0)*HH + lane);
    float w01 = __ldg(W + (d4+0)*HH + lane + 32);
    float w10 = __ldg(W + (d4+1)*HH + lane);
    float w11 = __ldg(W + (d4+1)*HH + lane + 32);
    float w20 = __ldg(W + (d4+2)*HH + lane);
    float w21 = __ldg(W + (d4+2)*HH + lane + 32);
    float w30 = __ldg(W + (d4+3)*HH + lane);
    float w31 = __ldg(W + (d4+3)*HH + lane + 32);
    #pragma unroll
    for (int r = 0; r < GRP; r++) {
      float4 b = *(const float4*)(rb + r*HH + d4);   // shared broadcast
      a0[r] += b.x*w00; a1[r] += b.x*w01;
      a0[r] += b.y*w10; a1[r] += b.y*w11;
      a0[r] += b.z*w20; a1[r] += b.z*w21;
      a0[r] += b.w*w30; a1[r] += b.w*w31;
    }
  }
}

// combine0: x1 = l2norm(xp0 + lrelu(y + bd0)); xd1 = x1 @ Wd1
__global__ void k_combine0(const float* __restrict__ bd, const float* __restrict__ Wdn) {
  __shared__ __align__(16) float rbuf[8][GRP*HH];
  int tid = threadIdx.x;
  int w = tid >> 5, lane = tid & 31;
  float* rb = &rbuf[w][0];
  int gw = (blockIdx.x*blockDim.x + tid) >> 5;
  int nw = (gridDim.x*blockDim.x) >> 5;
  float bd0 = __ldg(bd + lane), bd1 = __ldg(bd + lane + 32);
  const int NG = ROWS / GRP;
  for (int g = gw; g < NG; g += nw) {
    size_t row0 = (size_t)g * GRP;
    #pragma unroll
    for (int r = 0; r < GRP; r++) {
      size_t base = (row0 + r)*HH;
      float v0 = g_xp[base+lane]    + lrelu(g_y[base+lane]    + bd0);
      float v1 = g_xp[base+lane+32] + lrelu(g_y[base+lane+32] + bd1);
      float ss = warp_sum(v0*v0 + v1*v1);
      float rn = rsqrtf(fmaxf(ss, 1e-12f));
      v0 *= rn; v1 *= rn;
      g_x[base+lane] = v0; g_x[base+lane+32] = v1;
      rb[r*HH+lane] = v0;  rb[r*HH+lane+32] = v1;
    }
    __syncwarp();
    float a0[GRP], a1[GRP];
    #pragma unroll
    for (int r = 0; r < GRP; r++) { a0[r] = 0.f; a1[r] = 0.f; }
    matvec_grp(Wdn, rb, lane, a0, a1);
    #pragma unroll
    for (int r = 0; r < GRP; r++) {
      size_t base = (row0 + r)*HH;
      g_xd[base+lane] = a0[r]; g_xd[base+lane+32] = a1[r];
    }
    __syncwarp();
  }
}

// combine (layers 1,2): x' = l2norm(x@Wp + bp + lrelu(y + bd)); if !LAST xd = x' @ Wdn
template<bool LAST>
__global__ void k_combine(const float* __restrict__ Wp, const float* __restrict__ bp,
                          const float* __restrict__ bd, const float* __restrict__ Wdn) {
  __shared__ __align__(16) float rbuf[8][GRP*HH];
  int tid = threadIdx.x;
  int w = tid >> 5, lane = tid & 31;
  float* rb = &rbuf[w][0];
  int gw = (blockIdx.x*blockDim.x + tid) >> 5;
  int nw = (gridDim.x*blockDim.x) >> 5;
  float bp0 = __ldg(bp + lane), bp1 = __ldg(bp + lane + 32);
  float bd0 = __ldg(bd + lane), bd1 = __ldg(bd + lane + 32);
  const int NG = ROWS / GRP;
  for (int g = gw; g < NG; g += nw) {
    size_t row0 = (size_t)g * GRP;
    #pragma unroll
    for (int r = 0; r < GRP; r++) {
      size_t base = (row0 + r)*HH;
      rb[r*HH+lane]    = g_x[base+lane];
      rb[r*HH+lane+32] = g_x[base+lane+32];
    }
    __syncwarp();
    float a0[GRP], a1[GRP];
    #pragma unroll
    for (int r = 0; r < GRP; r++) { a0[r] = bp0; a1[r] = bp1; }
    matvec_grp(Wp, rb, lane, a0, a1);
    __syncwarp();
    #pragma unroll
    for (int r = 0; r < GRP; r++) {
      size_t base = (row0 + r)*HH;
      float v0 = a0[r] + lrelu(g_y[base+lane]    + bd0);
      float v1 = a1[r] + lrelu(g_y[base+lane+32] + bd1);
      float ss = warp_sum(v0*v0 + v1*v1);
      float rn = rsqrtf(fmaxf(ss, 1e-12f));
      v0 *= rn; v1 *= rn;
      g_x[base+lane] = v0; g_x[base+lane+32] = v1;
      if (!LAST) { rb[r*HH+lane] = v0; rb[r*HH+lane+32] = v1; }
    }
    if (!LAST) {
      __syncwarp();
      #pragma unroll
      for (int r = 0; r < GRP; r++) { a0[r] = 0.f; a1[r] = 0.f; }
      matvec_grp(Wdn, rb, lane, a0, a1);
      #pragma unroll
      for (int r = 0; r < GRP; r++) {
        size_t base = (row0 + r)*HH;
        g_xd[base+lane] = a0[r]; g_xd[base+lane+32] = a1[r];
      }
    }
    __syncwarp();
  }
}

// ---------------- pooling over sorted graph_ids ----------------
__device__ __forceinline__ int lower_bound_dev(const int* __restrict__ a, int n, int key) {
  int lo = 0, hi = n;
  while (lo < hi) { int m = (lo + hi) >> 1; if (a[m] < key) lo = m + 1; else hi = m; }
  return lo;
}

__global__ void k_pool(const int* __restrict__ gid) {
  __shared__ float red[256];
  int b = blockIdx.x / CC;
  int c = blockIdx.x - b*CC;
  int lo = lower_bound_dev(gid, NN, b);
  int hi = lower_bound_dev(gid, NN, b+1);
  int h   = threadIdx.x & 63;
  int sub = threadIdx.x >> 6;   // 0..3
  float acc = 0.f;
  const float* xs = g_x + (size_t)c*NN*HH;
  for (int n = lo + sub; n < hi; n += 4) acc += xs[(size_t)n*HH + h];
  red[threadIdx.x] = acc;
  __syncthreads();
  if (sub == 0)
    g_pooled[(size_t)blockIdx.x*HH + h] = red[h] + red[64+h] + red[128+h] + red[192+h];
}

// ---------------- final MLP: 64 -> 64 -> 64 -> 1 ----------------
__global__ void k_mlp(const float* __restrict__ Wm0, const float* __restrict__ bm0,
                      const float* __restrict__ Wm1, const float* __restrict__ bm1,
                      const float* __restrict__ Wm2, const float* __restrict__ bm2,
                      float* __restrict__ out) {
  __shared__ float s_in[HH], s_h[HH], rr[HH];
  int bc = blockIdx.x;
  int h = threadIdx.x;
  s_in[h] = g_pooled[(size_t)bc*HH + h];
  __syncthreads();
  float a = __ldg(bm0 + h);
  #pragma unroll 8
  for (int d = 0; d < HH; d++) a += s_in[d] * __ldg(Wm0 + d*HH + h);
  a = lrelu(a);
  s_h[h] = a;
  __syncthreads();
  float a2 = __ldg(bm1 + h);
  #pragma unroll 8
  for (int d = 0; d < HH; d++) a2 += s_h[d] * __ldg(Wm1 + d*HH + h);
  a2 = lrelu(a2);
  rr[h] = a2 * __ldg(Wm2 + h);
  __syncthreads();
  if (h < 32) {
    float v = rr[h] + rr[h+32];
    v = warp_sum(v);
    if (h == 0) out[bc] = v + __ldg(bm2);
  }
}

// ---------------- host orchestration ----------------
extern "C" void kernel_launch(void* const* d_in, const int* in_sizes, int n_in,
                              void* d_out, int out_size) {
  (void)in_sizes; (void)n_in; (void)out_size;
  const float* node_feats   = (const float*)d_in[0];
  const float* config_feats = (const float*)d_in[1];
  const int*   op_ids       = (const int*)  d_in[2];
  const int*   src          = (const int*)  d_in[3];
  const int*   dst          = (const int*)  d_in[4];
  const int*   graph_ids    = (const int*)  d_in[5];
  const float* op_emb       = (const float*)d_in[6];
  const float* W_d0 = (const float*)d_in[7];  const float* b_d0 = (const float*)d_in[8];
  const float* W_p0 = (const float*)d_in[9];  const float* b_p0 = (const float*)d_in[10];
  const float* W_d1 = (const float*)d_in[11]; const float* b_d1 = (const float*)d_in[12];
  const float* W_p1 = (const float*)d_in[13]; const float* b_p1 = (const float*)d_in[14];
  const float* W_d2 = (const float*)d_in[15]; const float* b_d2 = (const float*)d_in[16];
  const float* W_p2 = (const float*)d_in[17]; const float* b_p2 = (const float*)d_in[18];
  const float* W_m0 = (const float*)d_in[19]; const float* b_m0 = (const float*)d_in[20];
  const float* W_m1 = (const float*)d_in[21]; const float* b_m1 = (const float*)d_in[22];
  const float* W_m2 = (const float*)d_in[23]; const float* b_m2 = (const float*)d_in[24];
  float* out = (float*)d_out;

  // CSR build (bidirectional adjacency)
  k_zero_counts<<<(NN+255)/256, 256>>>();
  k_count<<<(EE+255)/256, 256>>>(src, dst);
  k_scan<<<1, 1024>>>();
  k_fill<<<(EE+255)/256, 256>>>(src, dst);

  // layer 0: fused join + both projections
  k_layer0<<<1024, 256>>>(node_feats, config_feats, op_ids, op_emb, W_d0, W_p0, b_p0);
  k_spmm<<<2048, 256>>>();
  k_combine0<<<2048, 256>>>(b_d0, W_d1);

  // layer 1
  k_spmm<<<2048, 256>>>();
  k_combine<false><<<2048, 256>>>(W_p1, b_p1, b_d1, W_d2);

  // layer 2
  k_spmm<<<2048, 256>>>();
  k_combine<true><<<2048, 256>>>(W_p2, b_p2, b_d2, (const float*)nullptr);

  // pooling + MLP head
  k_pool<<<BB*CC, 256>>>(graph_ids);
  k_mlp<<<BB*CC, HH>>>(W_m0, b_m0, W_m1, b_m1, W_m2, b_m2, out);
}